// round 3
// baseline (speedup 1.0000x reference)
#include <cuda_runtime.h>
#include <cuda_bf16.h>
#include <mma.h>

using namespace nvcuda;

#define BATCH 16
#define SQ    1024
#define SKV   1024
#define HD    256

// ---- static device scratch (no allocations allowed) ----
__device__ __nv_bfloat16 g_qb[BATCH * SQ * HD];
__device__ __nv_bfloat16 g_kb[BATCH * SKV * HD];
__device__ float g_rowsum[BATCH * SQ];
__device__ float g_cpart[BATCH * 4 * SKV];    // partial column sums (4 q-chunks)
__device__ float g_outpart[BATCH * 8 * HD];   // partial GEMV outputs (8 k-chunks)

// ---------------------------------------------------------------------------
// K0: convert Q and K to bf16
// ---------------------------------------------------------------------------
__global__ void k_convert(const float* __restrict__ q, const float* __restrict__ k) {
    int i = (blockIdx.x * blockDim.x + threadIdx.x) * 4;
    float4 qv = *(const float4*)(q + i);
    float4 kv = *(const float4*)(k + i);
    __nv_bfloat162* qo = (__nv_bfloat162*)(g_qb + i);
    __nv_bfloat162* ko = (__nv_bfloat162*)(g_kb + i);
    qo[0] = __floats2bfloat162_rn(qv.x, qv.y);
    qo[1] = __floats2bfloat162_rn(qv.z, qv.w);
    ko[0] = __floats2bfloat162_rn(kv.x, kv.y);
    ko[1] = __floats2bfloat162_rn(kv.z, kv.w);
}

// ---------------------------------------------------------------------------
// K1: S = Q K^T (bf16 WMMA), e = mask ? exp(exp(S)/16) : 0, write e into the
//     p_attn output region, and accumulate deterministic per-row sums.
//     Block = 64 q-rows x full 1024 k (looped in 64-wide tiles). 128 threads.
// ---------------------------------------------------------------------------
#define LDA 264          // padded bf16 leading dim (multiple of 8)
#define LDS 68           // padded float leading dim for S buffer (multiple of 4)

__global__ void __launch_bounds__(128) k_scores(const int* __restrict__ mask,
                                                float* __restrict__ p_out) {
    extern __shared__ char smraw[];
    __nv_bfloat16* Qs = (__nv_bfloat16*)smraw;          // 64 x LDA
    __nv_bfloat16* Ks = Qs + 64 * LDA;                  // 64 x LDA
    float*         Sb = (float*)(Ks + 64 * LDA);        // 64 x LDS

    const int b   = blockIdx.y;
    const int q0  = blockIdx.x * 64;
    const int tid = threadIdx.x;
    const int warp = tid >> 5;
    const int wy = warp >> 1;   // 0..1 (32-row band)
    const int wx = warp & 1;    // 0..1 (32-col band)

    // load Q tile 64 x 256 (uint4 = 8 bf16)
    const __nv_bfloat16* Qg = g_qb + (size_t)(b * SQ + q0) * HD;
    for (int idx = tid; idx < 64 * (HD / 8); idx += 128) {
        int r = idx / (HD / 8), c8 = idx % (HD / 8);
        *(uint4*)(Qs + r * LDA + c8 * 8) = *(const uint4*)(Qg + r * HD + c8 * 8);
    }

    float rowacc = 0.0f;   // valid for tid < 64: row (tid)

    for (int kt = 0; kt < SKV / 64; kt++) {
        __syncthreads();   // Sb reduction + previous Ks use done; Q tile visible (1st iter)

        const __nv_bfloat16* Kg = g_kb + (size_t)(b * SKV + kt * 64) * HD;
        for (int idx = tid; idx < 64 * (HD / 8); idx += 128) {
            int r = idx / (HD / 8), c8 = idx % (HD / 8);
            *(uint4*)(Ks + r * LDA + c8 * 8) = *(const uint4*)(Kg + r * HD + c8 * 8);
        }
        __syncthreads();

        wmma::fragment<wmma::accumulator, 16, 16, 16, float> acc[2][2];
        #pragma unroll
        for (int i = 0; i < 2; i++)
            #pragma unroll
            for (int j = 0; j < 2; j++) wmma::fill_fragment(acc[i][j], 0.0f);

        #pragma unroll
        for (int dk = 0; dk < HD; dk += 16) {
            wmma::fragment<wmma::matrix_a, 16, 16, 16, __nv_bfloat16, wmma::row_major> af[2];
            wmma::fragment<wmma::matrix_b, 16, 16, 16, __nv_bfloat16, wmma::col_major> bf[2];
            #pragma unroll
            for (int i = 0; i < 2; i++)
                wmma::load_matrix_sync(af[i], Qs + (wy * 32 + i * 16) * LDA + dk, LDA);
            #pragma unroll
            for (int j = 0; j < 2; j++)
                wmma::load_matrix_sync(bf[j], Ks + (wx * 32 + j * 16) * LDA + dk, LDA);
            #pragma unroll
            for (int i = 0; i < 2; i++)
                #pragma unroll
                for (int j = 0; j < 2; j++)
                    wmma::mma_sync(acc[i][j], af[i], bf[j], acc[i][j]);
        }

        #pragma unroll
        for (int i = 0; i < 2; i++)
            #pragma unroll
            for (int j = 0; j < 2; j++)
                wmma::store_matrix_sync(Sb + (wy * 32 + i * 16) * LDS + (wx * 32 + j * 16),
                                        acc[i][j], LDS, wmma::mem_row_major);
        __syncthreads();

        // elementwise: e = mask ? exp(exp(s) * (1/16)) : 0
        const int* mrow = mask + (size_t)(b * SQ + q0) * SKV + kt * 64;
        float* prow = p_out + (size_t)(b * SQ + q0) * SKV + kt * 64;
        for (int idx = tid; idx < 64 * 64; idx += 128) {
            int r = idx >> 6, c = idx & 63;
            float s = Sb[r * LDS + c];
            int m = mrow[(size_t)r * SKV + c];
            float ev = m ? expf(expf(s) * 0.0625f) : 0.0f;
            prow[(size_t)r * SKV + c] = ev;
            Sb[r * LDS + c] = ev;
        }
        __syncthreads();

        // deterministic row reduction: thread t owns row t, serial over 64 cols
        if (tid < 64) {
            float ssum = 0.0f;
            #pragma unroll 8
            for (int c = 0; c < 64; c++) ssum += Sb[tid * LDS + c];
            rowacc += ssum;
        }
    }

    if (tid < 64) g_rowsum[b * SQ + q0 + tid] = rowacc;
}

// ---------------------------------------------------------------------------
// K2: p = e / rowsum (in place), and partial column sums over 256-row q-chunks.
//     Grid: (k-chunk 4, q-chunk 4, batch 16). 256 threads, thread t owns one k.
// ---------------------------------------------------------------------------
__global__ void __launch_bounds__(256) k_norm(float* __restrict__ p) {
    const int b  = blockIdx.z;
    const int yq = blockIdx.y;
    const int kc = blockIdx.x;
    const int k  = kc * 256 + threadIdx.x;

    __shared__ float sinv[256];
    sinv[threadIdx.x] = 1.0f / g_rowsum[b * SQ + yq * 256 + threadIdx.x];
    __syncthreads();

    float* pp = p + ((size_t)b * SQ + yq * 256) * SKV + k;
    float acc = 0.0f;
    #pragma unroll 4
    for (int q = 0; q < 256; q++) {
        float v = pp[(size_t)q * SKV] * sinv[q];
        pp[(size_t)q * SKV] = v;
        acc += v;
    }
    g_cpart[(size_t)(b * 4 + yq) * SKV + k] = acc;
}

// ---------------------------------------------------------------------------
// K3: out_part[b,chunk,d] = sum_{k in chunk} c[b,k] * V[b,k,d]
//     c[b,k] = sum over the 4 q-chunk partials (reduced here, deterministically)
//     Grid: (8 k-chunks, 16 batches). 256 threads (one per d).
// ---------------------------------------------------------------------------
__global__ void __launch_bounds__(256) k_gemv(const float* __restrict__ v) {
    const int b  = blockIdx.y;
    const int ch = blockIdx.x;      // 128 k per chunk
    const int t  = threadIdx.x;

    __shared__ float cv[128];
    if (t < 128) {
        int k = ch * 128 + t;
        float s = 0.0f;
        #pragma unroll
        for (int y = 0; y < 4; y++) s += g_cpart[(size_t)(b * 4 + y) * SKV + k];
        cv[t] = s;
    }
    __syncthreads();

    const float* vb = v + ((size_t)b * SKV + ch * 128) * HD + t;
    float acc = 0.0f;
    #pragma unroll 8
    for (int k = 0; k < 128; k++) acc += cv[k] * vb[(size_t)k * HD];
    g_outpart[(size_t)(b * 8 + ch) * HD + t] = acc;
}

// ---------------------------------------------------------------------------
// K4: final 8-way reduce into d_out[0 : B*HD]
// ---------------------------------------------------------------------------
__global__ void k_final(float* __restrict__ out) {
    int i = blockIdx.x * blockDim.x + threadIdx.x;   // 4096
    int b = i / HD, d = i % HD;
    float s = 0.0f;
    #pragma unroll
    for (int c = 0; c < 8; c++) s += g_outpart[(size_t)(b * 8 + c) * HD + d];
    out[i] = s;
}

// ---------------------------------------------------------------------------
extern "C" void kernel_launch(void* const* d_in, const int* in_sizes, int n_in,
                              void* d_out, int out_size) {
    const float* q    = (const float*)d_in[0];
    const float* k    = (const float*)d_in[1];
    const float* v    = (const float*)d_in[2];
    const int*   mask = (const int*)d_in[3];

    float* out = (float*)d_out;             // [0 : B*HD)            = output.sum(axis=1)
    float* p   = out + BATCH * HD;          // [B*HD : B*HD+B*SQ*SKV) = p_attn

    const size_t smem1 = (size_t)(2 * 64 * LDA) * sizeof(__nv_bfloat16)
                       + (size_t)(64 * LDS) * sizeof(float);
    cudaFuncSetAttribute(k_scores, cudaFuncAttributeMaxDynamicSharedMemorySize, (int)smem1);

    k_convert<<<BATCH * SQ * HD / 4 / 256, 256>>>(q, k);
    k_scores<<<dim3(SQ / 64, BATCH), 128, smem1>>>(mask, p);
    k_norm<<<dim3(SKV / 256, SQ / 256, BATCH), 256>>>(p);
    k_gemv<<<dim3(8, BATCH), 256>>>(v);
    k_final<<<BATCH * HD / 256, 256>>>(out);
}

// round 5
// speedup vs baseline: 1.6842x; 1.6842x over previous
#include <cuda_runtime.h>
#include <cuda_bf16.h>
#include <mma.h>

using namespace nvcuda;

#define BATCH 16
#define SQ    1024
#define SKV   1024
#define HD    256

#define QT 32              // q-rows per block (tile held fully in smem)
#define KT 64              // k-tile width per iteration
#define NKT (SKV / KT)     // 16
#define LDA 264            // padded bf16 leading dim

// ---- static device scratch ----
__device__ __nv_bfloat16 g_qb[BATCH * SQ * HD];
__device__ __nv_bfloat16 g_kb[BATCH * SKV * HD];
__device__ float g_cpart[BATCH * 32 * SKV];    // per-qtile column partial sums
__device__ float g_csum[BATCH * SKV];          // reduced column sums
__device__ float g_outpart[BATCH * 32 * HD];   // per-kchunk GEMV partials

// ---------------------------------------------------------------------------
// K0: convert Q and K to bf16
// ---------------------------------------------------------------------------
__global__ void k_convert(const float* __restrict__ q, const float* __restrict__ k) {
    int i = (blockIdx.x * blockDim.x + threadIdx.x) * 4;
    float4 qv = *(const float4*)(q + i);
    float4 kv = *(const float4*)(k + i);
    __nv_bfloat162* qo = (__nv_bfloat162*)(g_qb + i);
    __nv_bfloat162* ko = (__nv_bfloat162*)(g_kb + i);
    qo[0] = __floats2bfloat162_rn(qv.x, qv.y);
    qo[1] = __floats2bfloat162_rn(qv.z, qv.w);
    ko[0] = __floats2bfloat162_rn(kv.x, kv.y);
    ko[1] = __floats2bfloat162_rn(kv.z, kv.w);
}

// ---------------------------------------------------------------------------
// K1 (fused): per block = 32 q-rows x full 1024 k.
//   S = QK^T (WMMA bf16, 8 warps in 2x4 grid of 16x16 frags),
//   e = mask ? exp(exp(S)/16) : 0 kept in a 128KB smem tile,
//   deterministic rowsum, normalize in smem, single coalesced write of p,
//   plus per-block column partial sums for the output GEMV.
//   K tiles double-buffered through registers; mask prefetched before MMA.
// ---------------------------------------------------------------------------
__global__ void __launch_bounds__(256) k_main(const int* __restrict__ mask,
                                              float* __restrict__ p_out) {
    extern __shared__ char smraw[];
    __nv_bfloat16* Qs = (__nv_bfloat16*)smraw;           // QT x LDA
    __nv_bfloat16* Ks = Qs + QT * LDA;                   // KT x LDA
    float*         Sb = (float*)(Ks + KT * LDA);         // QT x SKV  (128 KB)
    float*         rs    = Sb + QT * SKV;                // QT
    float*         sinvs = rs + QT;                      // QT

    const int b    = blockIdx.y;
    const int qt   = blockIdx.x;
    const int q0   = qt * QT;
    const int tid  = threadIdx.x;
    const int lane = tid & 31;
    const int warp = tid >> 5;
    const int wy   = warp >> 2;     // 0..1 : 16-row band
    const int wx   = warp & 3;      // 0..3 : 16-col band

    // load Q tile (32 x 256 bf16)
    const __nv_bfloat16* Qg = g_qb + (size_t)(b * SQ + q0) * HD;
    for (int s = tid; s < QT * (HD / 8); s += 256) {
        int r = s >> 5, c8 = s & 31;
        *(uint4*)(Qs + r * LDA + c8 * 8) = *(const uint4*)(Qg + r * HD + c8 * 8);
    }

    // prefetch K tile 0 into registers (64 x 256 bf16 = 8 uint4/thread)
    const __nv_bfloat16* Kg = g_kb + (size_t)b * SKV * HD;
    uint4 kreg[8];
    #pragma unroll
    for (int j = 0; j < 8; j++) {
        int s = tid + j * 256; int r = s >> 5, c8 = s & 31;
        kreg[j] = *(const uint4*)(Kg + r * HD + c8 * 8);
    }

    for (int kt = 0; kt < NKT; kt++) {
        __syncthreads();                       // Ks free (prev MMA done)
        #pragma unroll
        for (int j = 0; j < 8; j++) {
            int s = tid + j * 256; int r = s >> 5, c8 = s & 31;
            *(uint4*)(Ks + r * LDA + c8 * 8) = kreg[j];
        }
        __syncthreads();                       // Ks ready

        if (kt + 1 < NKT) {                    // prefetch next K tile (hidden under MMA)
            const __nv_bfloat16* Kn = Kg + (size_t)(kt + 1) * KT * HD;
            #pragma unroll
            for (int j = 0; j < 8; j++) {
                int s = tid + j * 256; int r = s >> 5, c8 = s & 31;
                kreg[j] = *(const uint4*)(Kn + r * HD + c8 * 8);
            }
        }

        // prefetch this warp's 16x16 mask region (hidden under MMA)
        const int* mb = mask + (size_t)(b * SQ + q0 + wy * 16) * SKV + kt * KT + wx * 16;
        int mreg[8];
        #pragma unroll
        for (int i = 0; i < 8; i++) {
            int rl = i * 2 + (lane >> 4), c = lane & 15;
            mreg[i] = mb[(size_t)rl * SKV + c];
        }

        // MMA: 16x16 accumulator per warp, 16 k-steps
        wmma::fragment<wmma::accumulator, 16, 16, 16, float> acc;
        wmma::fill_fragment(acc, 0.0f);
        #pragma unroll
        for (int dk = 0; dk < HD; dk += 16) {
            wmma::fragment<wmma::matrix_a, 16, 16, 16, __nv_bfloat16, wmma::row_major> af;
            wmma::fragment<wmma::matrix_b, 16, 16, 16, __nv_bfloat16, wmma::col_major> bf;
            wmma::load_matrix_sync(af, Qs + (wy * 16) * LDA + dk, LDA);
            wmma::load_matrix_sync(bf, Ks + (wx * 16) * LDA + dk, LDA);
            wmma::mma_sync(acc, af, bf, acc);
        }
        float* St = Sb + (size_t)(wy * 16) * SKV + kt * KT + wx * 16;
        wmma::store_matrix_sync(St, acc, SKV, wmma::mem_row_major);
        __syncwarp();

        // elementwise on own region: e = mask ? exp(exp(s)/16) : 0
        #pragma unroll
        for (int i = 0; i < 8; i++) {
            int rl = i * 2 + (lane >> 4), c = lane & 15;
            float s = St[rl * SKV + c];
            float ev = mreg[i] ? expf(expf(s) * 0.0625f) : 0.0f;
            St[rl * SKV + c] = ev;
        }
    }
    __syncthreads();

    // deterministic rowsum: warp w owns rows 4w..4w+3
    #pragma unroll
    for (int rr = 0; rr < 4; rr++) {
        int r = warp * 4 + rr;
        float ssum = 0.0f;
        #pragma unroll 8
        for (int j = 0; j < SKV / 32; j++) ssum += Sb[(size_t)r * SKV + lane + j * 32];
        #pragma unroll
        for (int o = 16; o > 0; o >>= 1) ssum += __shfl_xor_sync(0xffffffffu, ssum, o);
        if (lane == 0) rs[r] = ssum;
    }
    __syncthreads();
    if (tid < QT) sinvs[tid] = 1.0f / rs[tid];
    __syncthreads();

    // normalize in smem, single coalesced write of p, column partial sums
    float* prow = p_out + (size_t)(b * SQ + q0) * SKV;
    float4 ca = {0.f, 0.f, 0.f, 0.f};
    #pragma unroll 4
    for (int r = 0; r < QT; r++) {
        float4 v = *(float4*)&Sb[(size_t)r * SKV + tid * 4];
        float s = sinvs[r];
        v.x *= s; v.y *= s; v.z *= s; v.w *= s;
        *(float4*)&prow[(size_t)r * SKV + tid * 4] = v;
        ca.x += v.x; ca.y += v.y; ca.z += v.z; ca.w += v.w;
    }
    *(float4*)&g_cpart[(size_t)(b * 32 + qt) * SKV + tid * 4] = ca;
}

// ---------------------------------------------------------------------------
// K2: reduce 32 q-tile column partials -> g_csum[b,k]
// ---------------------------------------------------------------------------
__global__ void __launch_bounds__(256) k_csum() {
    int i = blockIdx.x * 256 + threadIdx.x;      // B*SKV = 16384
    int b = i / SKV, k = i % SKV;
    float s = 0.0f;
    #pragma unroll
    for (int y = 0; y < 32; y++) s += g_cpart[(size_t)(b * 32 + y) * SKV + k];
    g_csum[i] = s;
}

// ---------------------------------------------------------------------------
// K3: out_part[b,ch,d] = sum_{k in 32-chunk} csum[b,k] * V[b,k,d]
// ---------------------------------------------------------------------------
__global__ void __launch_bounds__(256) k_gemv(const float* __restrict__ v) {
    const int b  = blockIdx.y;
    const int ch = blockIdx.x;     // 32 k per chunk
    const int t  = threadIdx.x;

    __shared__ float cv[32];
    if (t < 32) cv[t] = g_csum[b * SKV + ch * 32 + t];
    __syncthreads();

    const float* vb = v + ((size_t)b * SKV + ch * 32) * HD + t;
    float acc = 0.0f;
    #pragma unroll
    for (int k = 0; k < 32; k++) acc += cv[k] * vb[(size_t)k * HD];
    g_outpart[(size_t)(b * 32 + ch) * HD + t] = acc;
}

// ---------------------------------------------------------------------------
// K4: final 32-way reduce into d_out[0 : B*HD]
// ---------------------------------------------------------------------------
__global__ void k_final(float* __restrict__ out) {
    int i = blockIdx.x * blockDim.x + threadIdx.x;   // 4096
    int b = i / HD, d = i % HD;
    float s = 0.0f;
    #pragma unroll
    for (int c = 0; c < 32; c++) s += g_outpart[(size_t)(b * 32 + c) * HD + d];
    out[i] = s;
}

// ---------------------------------------------------------------------------
extern "C" void kernel_launch(void* const* d_in, const int* in_sizes, int n_in,
                              void* d_out, int out_size) {
    const float* q    = (const float*)d_in[0];
    const float* k    = (const float*)d_in[1];
    const float* v    = (const float*)d_in[2];
    const int*   mask = (const int*)d_in[3];

    float* out = (float*)d_out;             // [0 : B*HD)             = output.sum(axis=1)
    float* p   = out + BATCH * HD;          // [B*HD : B*HD+B*SQ*SKV) = p_attn

    const size_t smem1 = (size_t)(QT * LDA + KT * LDA) * sizeof(__nv_bfloat16)
                       + (size_t)(QT * SKV + 2 * QT) * sizeof(float);
    cudaFuncSetAttribute(k_main, cudaFuncAttributeMaxDynamicSharedMemorySize, (int)smem1);

    k_convert<<<BATCH * SQ * HD / 4 / 256, 256>>>(q, k);
    k_main<<<dim3(SQ / QT, BATCH), 256, smem1>>>(mask, p);
    k_csum<<<BATCH * SKV / 256, 256>>>();
    k_gemv<<<dim3(32, BATCH), 256>>>(v);
    k_final<<<BATCH * HD / 256, 256>>>(out);
}